// round 1
// baseline (speedup 1.0000x reference)
#include <cuda_runtime.h>
#include <math.h>

#define BATCH 8
#define VDIM 5000
#define CDIM 256
#define KDIM 200

// Scratch (device globals: no allocation allowed)
__device__ float g_A [BATCH*KDIM*CDIM];   // A  = evecs_trans_x @ feat_x   [b,k,c]
__device__ float g_Bc[BATCH*KDIM*CDIM];   // Bc = evecs_trans_y @ feat_y   [b,k,c]
__device__ float g_S [BATCH*KDIM*KDIM];   // S  = A @ A^T                  [b,k,l]
__device__ float g_R [BATCH*KDIM*KDIM];   // R  = Bc @ A^T                 [b,k,l]

// ---------------------------------------------------------------------------
// Kernel 1: A[b,k,c] = sum_v E[b,k,v] * F[b,v,c]   (M=200, N=256, K=5000)
// BM=64, BN=64, BK=8, 128 threads, 8x4 register tile per thread.
// grid (4, 4, 16) ; z = b + 8*which  (which: 0 -> x/A, 1 -> y/Bc)
// ---------------------------------------------------------------------------
__global__ __launch_bounds__(128) void k_gemm_feat(
    const float* __restrict__ fx, const float* __restrict__ fy,
    const float* __restrict__ ex, const float* __restrict__ ey)
{
    const int bz    = blockIdx.z;
    const int b     = bz & 7;
    const int which = bz >> 3;
    const float* E = (which ? ey : ex) + (size_t)b*KDIM*VDIM;
    const float* F = (which ? fy : fx) + (size_t)b*VDIM*CDIM;
    float*       C = (which ? g_Bc : g_A) + (size_t)b*KDIM*CDIM;

    const int m0 = blockIdx.y * 64;
    const int n0 = blockIdx.x * 64;

    __shared__ float As[8][64];   // As[v][k]
    __shared__ float Bs[8][64];   // Bs[v][c]

    const int tid = threadIdx.x;
    const int tx  = tid & 15;     // 0..15 -> n
    const int ty  = tid >> 4;     // 0..7  -> m

    float acc[8][4];
    #pragma unroll
    for (int i = 0; i < 8; ++i)
        #pragma unroll
        for (int j = 0; j < 4; ++j) acc[i][j] = 0.f;

    const int lrow = tid >> 1;         // 0..63 (k row of E tile)
    const int lv4  = (tid & 1) * 4;    // 0 or 4 (v offset)
    const int fvr  = tid >> 4;         // 0..7  (v row of F tile)
    const int fc4  = (tid & 15) * 4;   // 0..60 (c offset)

    for (int v0 = 0; v0 < VDIM; v0 += 8) {
        float4 ea = make_float4(0.f, 0.f, 0.f, 0.f);
        if (m0 + lrow < KDIM)
            ea = *reinterpret_cast<const float4*>(E + (size_t)(m0 + lrow)*VDIM + v0 + lv4);
        float4 fb = *reinterpret_cast<const float4*>(F + (size_t)(v0 + fvr)*CDIM + n0 + fc4);

        __syncthreads();
        As[lv4+0][lrow] = ea.x; As[lv4+1][lrow] = ea.y;
        As[lv4+2][lrow] = ea.z; As[lv4+3][lrow] = ea.w;
        *reinterpret_cast<float4*>(&Bs[fvr][fc4]) = fb;
        __syncthreads();

        #pragma unroll
        for (int kk = 0; kk < 8; ++kk) {
            float4 a0 = *reinterpret_cast<const float4*>(&As[kk][ty*8]);
            float4 a1 = *reinterpret_cast<const float4*>(&As[kk][ty*8+4]);
            float4 bb = *reinterpret_cast<const float4*>(&Bs[kk][tx*4]);
            float am[8] = {a0.x,a0.y,a0.z,a0.w,a1.x,a1.y,a1.z,a1.w};
            float bn[4] = {bb.x,bb.y,bb.z,bb.w};
            #pragma unroll
            for (int i2 = 0; i2 < 8; ++i2)
                #pragma unroll
                for (int j2 = 0; j2 < 4; ++j2)
                    acc[i2][j2] = fmaf(am[i2], bn[j2], acc[i2][j2]);
        }
    }

    #pragma unroll
    for (int i2 = 0; i2 < 8; ++i2) {
        int k = m0 + ty*8 + i2;
        if (k < KDIM) {
            float4 v = make_float4(acc[i2][0], acc[i2][1], acc[i2][2], acc[i2][3]);
            *reinterpret_cast<float4*>(C + (size_t)k*CDIM + n0 + tx*4) = v;
        }
    }
}

// ---------------------------------------------------------------------------
// Kernel 2: S[b] = A A^T, R[b] = Bc A^T   (200x200x256)
// BM=BN=64, BK=16, 256 threads, 4x4 tiles.  grid (4,4,16); z = b + 8*which
// ---------------------------------------------------------------------------
__global__ __launch_bounds__(256) void k_gemm_gram()
{
    const int bz    = blockIdx.z;
    const int b     = bz & 7;
    const int which = bz >> 3;
    const float* X = (which ? g_Bc : g_A) + (size_t)b*KDIM*CDIM;
    const float* Y = g_A + (size_t)b*KDIM*CDIM;
    float*       C = (which ? g_R : g_S) + (size_t)b*KDIM*KDIM;

    const int m0 = blockIdx.y * 64;
    const int n0 = blockIdx.x * 64;

    __shared__ float As[16][64];
    __shared__ float Bs[16][64];

    const int tid = threadIdx.x;
    const int tx  = tid & 15;
    const int ty  = tid >> 4;
    const int lr  = tid >> 2;        // 0..63
    const int lc4 = (tid & 3) * 4;   // 0..12

    float acc[4][4];
    #pragma unroll
    for (int i = 0; i < 4; ++i)
        #pragma unroll
        for (int j = 0; j < 4; ++j) acc[i][j] = 0.f;

    for (int c0 = 0; c0 < CDIM; c0 += 16) {
        float4 xa = make_float4(0.f,0.f,0.f,0.f), yb = make_float4(0.f,0.f,0.f,0.f);
        if (m0 + lr < KDIM) xa = *reinterpret_cast<const float4*>(X + (size_t)(m0+lr)*CDIM + c0 + lc4);
        if (n0 + lr < KDIM) yb = *reinterpret_cast<const float4*>(Y + (size_t)(n0+lr)*CDIM + c0 + lc4);
        __syncthreads();
        As[lc4+0][lr] = xa.x; As[lc4+1][lr] = xa.y; As[lc4+2][lr] = xa.z; As[lc4+3][lr] = xa.w;
        Bs[lc4+0][lr] = yb.x; Bs[lc4+1][lr] = yb.y; Bs[lc4+2][lr] = yb.z; Bs[lc4+3][lr] = yb.w;
        __syncthreads();
        #pragma unroll
        for (int kk = 0; kk < 16; ++kk) {
            float4 a  = *reinterpret_cast<const float4*>(&As[kk][ty*4]);
            float4 bb = *reinterpret_cast<const float4*>(&Bs[kk][tx*4]);
            float am[4] = {a.x,a.y,a.z,a.w}, bn[4] = {bb.x,bb.y,bb.z,bb.w};
            #pragma unroll
            for (int i2 = 0; i2 < 4; ++i2)
                #pragma unroll
                for (int j2 = 0; j2 < 4; ++j2)
                    acc[i2][j2] = fmaf(am[i2], bn[j2], acc[i2][j2]);
        }
    }

    for (int i2 = 0; i2 < 4; ++i2) {
        int k = m0 + ty*4 + i2;
        if (k >= KDIM) continue;
        for (int j2 = 0; j2 < 4; ++j2) {
            int l = n0 + tx*4 + j2;
            if (l >= KDIM) continue;
            C[(size_t)k*KDIM + l] = acc[i2][j2];
        }
    }
}

// ---------------------------------------------------------------------------
// Kernel 3: per-(b,i) SPD solve via blocked Cholesky in shared memory.
// One CTA per system, 256 threads. Lower triangle only.
// grid (200, 8).
// ---------------------------------------------------------------------------
#define LDA 204     // row stride (mult of 4 for float4; 204 mod 32 = 12 -> mild conflicts only)
#define NB  20      // panel width (200 / 20 = 10 panels)
#define SOLVE_SMEM_FLOATS (KDIM*LDA + NB*KDIM + KDIM + KDIM + 32)
#define SOLVE_SMEM_BYTES  (SOLVE_SMEM_FLOATS * 4)

__global__ __launch_bounds__(256) void k_solve(
    const float* __restrict__ evx_all, const float* __restrict__ evy_all,
    const float* __restrict__ p_gamma, const float* __restrict__ p_lambda,
    float* __restrict__ out)
{
    extern __shared__ float sh[];
    float* Msh  = sh;                         // [200][204] lower triangle
    float* Psh  = Msh + KDIM*LDA;             // [NB][200]  compact panel (transposed)
    float* rhs  = Psh + NB*KDIM;              // [200]
    float* dinv = rhs + KDIM;                 // [200] 1/L[k][k]
    float* red  = dinv + KDIM;                // [32] reduction scratch

    const int irow = blockIdx.x;              // i in D[b, i, :]
    const int b    = blockIdx.y;
    const int tid  = threadIdx.x;
    const int lane = tid & 31;
    const int wid  = tid >> 5;

    const float* evx = evx_all + b*KDIM;
    const float* evy = evy_all + b*KDIM;

    // gamma = sigmoid(gamma_raw); lambda = clip(10 + softplus(l)*990/1000, 10, 1000)
    const float graw  = p_gamma[0];
    const float lraw  = p_lambda[0];
    const float gamma = 1.f / (1.f + expf(-graw));
    const float sp    = fmaxf(lraw, 0.f) + log1pf(expf(-fabsf(lraw)));  // stable softplus
    float lmbda = 10.f + sp * (1000.f - 10.f) / 1000.f;
    lmbda = fminf(fmaxf(lmbda, 10.f), 1000.f);

    // scaling = max(max(evals_x[b]), max(evals_y[b]))
    float mv = 0.f;
    for (int j = tid; j < KDIM; j += 256) mv = fmaxf(mv, fmaxf(evx[j], evy[j]));
    #pragma unroll
    for (int o = 16; o > 0; o >>= 1) mv = fmaxf(mv, __shfl_xor_sync(0xffffffffu, mv, o));
    if (lane == 0) red[wid] = mv;
    __syncthreads();
    if (tid == 0) {
        float m2 = red[0];
        for (int w = 1; w < 8; ++w) m2 = fmaxf(m2, red[w]);
        red[0] = m2;
    }
    __syncthreads();
    const float scaling = red[0];

    const float gx = powf(evx[irow] / scaling, gamma);
    const float dx = 1.f / (gx*gx + 1.f);

    // Load M = S + lmbda * D[b, irow, :] on the diagonal (lower triangle only)
    const float* Sb = g_S + (size_t)b*KDIM*KDIM;
    for (int idx = tid; idx < KDIM*KDIM; idx += 256) {
        int r = idx / KDIM;
        int c = idx - r*KDIM;
        if (c > r) continue;
        float v = Sb[idx];
        if (c == r) {
            float gy  = powf(evy[r] / scaling, gamma);
            float dy  = 1.f / (gy*gy + 1.f);
            float mre = gy*dy - gx*dx;
            float mim = dy - dx;
            v += lmbda * (mre*mre + mim*mim);
        }
        Msh[r*LDA + c] = v;
    }
    if (tid < KDIM) rhs[tid] = g_R[(size_t)b*KDIM*KDIM + (size_t)irow*KDIM + tid];

    // --- Blocked Cholesky (right-looking; left-looking within panel) ---
    for (int p = 0; p < KDIM/NB; ++p) {
        const int k0 = p * NB;
        for (int kk = 0; kk < NB; ++kk) {
            const int k = k0 + kk;
            __syncthreads();
            // All threads compute updated diagonal (broadcast reads, identical results)
            float lrowv[NB];
            float vk = Msh[k*LDA + k];
            for (int m = 0; m < kk; ++m) {
                float lv = Msh[k*LDA + k0 + m];
                lrowv[m] = lv;
                vk -= lv * lv;
            }
            const float s   = sqrtf(vk);
            const float inv = 1.f / s;
            if (tid == 0) dinv[k] = inv;
            // Update + scale column k below diagonal
            for (int i = k + 1 + tid; i < KDIM; i += 256) {
                float v = Msh[i*LDA + k];
                for (int m = 0; m < kk; ++m) v -= Msh[i*LDA + k0 + m] * lrowv[m];
                Msh[i*LDA + k] = v * inv;
            }
        }
        __syncthreads();
        const int kend = k0 + NB;
        const int t    = KDIM - kend;
        if (t > 0) {
            // Compact panel -> Psh[kk][r] (r = trailing row index), conflict-free reads
            for (int idx = tid; idx < NB*t; idx += 256) {
                int kk = idx / t;
                int r  = idx - kk*t;
                Psh[kk*KDIM + r] = Msh[(kend + r)*LDA + k0 + kk];
            }
            __syncthreads();
            // Trailing rank-NB update, lower triangle, one thread per row
            const int i = kend + tid;
            if (i < KDIM) {
                const int r = i - kend;
                float a[NB];
                #pragma unroll
                for (int kk = 0; kk < NB; ++kk) a[kk] = Psh[kk*KDIM + r];
                float* row = Msh + i*LDA;
                int j = kend;
                for (; j + 3 <= i; j += 4) {
                    float4 c4 = *reinterpret_cast<float4*>(row + j);
                    #pragma unroll
                    for (int kk = 0; kk < NB; ++kk) {
                        float4 pv = *reinterpret_cast<const float4*>(Psh + kk*KDIM + (j - kend));
                        c4.x = fmaf(-a[kk], pv.x, c4.x);
                        c4.y = fmaf(-a[kk], pv.y, c4.y);
                        c4.z = fmaf(-a[kk], pv.z, c4.z);
                        c4.w = fmaf(-a[kk], pv.w, c4.w);
                    }
                    *reinterpret_cast<float4*>(row + j) = c4;
                }
                for (; j <= i; ++j) {
                    float cv = row[j];
                    #pragma unroll
                    for (int kk = 0; kk < NB; ++kk) cv -= a[kk] * Psh[kk*KDIM + (j - kend)];
                    row[j] = cv;
                }
            }
        }
    }
    __syncthreads();

    // --- Triangular solves, warp 0, warp-synchronous (no block barriers) ---
    if (wid == 0) {
        // Forward: L y = rhs
        for (int j = 0; j < KDIM; ++j) {
            float yj = __shfl_sync(0xffffffffu, rhs[j] * dinv[j], 0);
            for (int i2 = j + 1 + lane; i2 < KDIM; i2 += 32)
                rhs[i2] -= Msh[i2*LDA + j] * yj;
            if (lane == 0) rhs[j] = yj;
            __syncwarp();
        }
        // Backward: L^T x = y  (uses contiguous row j of L)
        for (int j = KDIM - 1; j >= 0; --j) {
            float xj = __shfl_sync(0xffffffffu, rhs[j] * dinv[j], 0);
            for (int i2 = lane; i2 < j; i2 += 32)
                rhs[i2] -= Msh[j*LDA + i2] * xj;
            if (lane == 0) rhs[j] = xj;
            __syncwarp();
        }
    }
    __syncthreads();

    for (int j = tid; j < KDIM; j += 256)
        out[((size_t)b*KDIM + irow)*KDIM + j] = rhs[j];
}

// ---------------------------------------------------------------------------
extern "C" void kernel_launch(void* const* d_in, const int* in_sizes, int n_in,
                              void* d_out, int out_size)
{
    const float* feat_x = (const float*)d_in[0];
    const float* feat_y = (const float*)d_in[1];
    const float* evals_x = (const float*)d_in[2];
    const float* evals_y = (const float*)d_in[3];
    const float* evtx = (const float*)d_in[4];
    const float* evty = (const float*)d_in[5];
    const float* graw = (const float*)d_in[6];
    const float* lraw = (const float*)d_in[7];
    float* out = (float*)d_out;

    k_gemm_feat<<<dim3(4, 4, 16), 128>>>(feat_x, feat_y, evtx, evty);
    k_gemm_gram<<<dim3(4, 4, 16), 256>>>();
    cudaFuncSetAttribute(k_solve, cudaFuncAttributeMaxDynamicSharedMemorySize, SOLVE_SMEM_BYTES);
    k_solve<<<dim3(KDIM, BATCH), 256, SOLVE_SMEM_BYTES>>>(evals_x, evals_y, graw, lraw, out);
}

// round 2
// speedup vs baseline: 1.7806x; 1.7806x over previous
#include <cuda_runtime.h>
#include <math.h>

#define BATCH 8
#define VDIM 5000
#define CDIM 256
#define KDIM 200
#define NB   20
#define NPAN (KDIM/NB)

// Scratch (device globals: no allocation allowed)
__device__ float g_A [BATCH*KDIM*CDIM];
__device__ float g_Bc[BATCH*KDIM*CDIM];
__device__ float g_S [BATCH*KDIM*KDIM];
__device__ float g_R [BATCH*KDIM*KDIM];

// Packed lower-triangle row offset: row i starts at offr(i), padded to float4.
// offr(i) = 4 * sum_{m=1..i} ceil(m/4) = 4*(q+1)*(2q+r), q=i>>2, r=i&3.
// Total floats = offr(200) = 20400.
__device__ __forceinline__ int offr(int i) {
    int q = i >> 2, r = i & 3;
    return ((q + 1) * ((q << 1) + r)) << 2;
}

// ---------------------------------------------------------------------------
// Kernel 1: A[b,k,c] = sum_v E[b,k,v] * F[b,v,c]   (M=200, N=256, K=5000)
// BM=64, BN=64, BK=8, 256 threads, 4x4 register tile, global prefetch.
// grid (4, 4, 16) ; z = b + 8*which
// ---------------------------------------------------------------------------
__global__ __launch_bounds__(256) void k_gemm_feat(
    const float* __restrict__ fx, const float* __restrict__ fy,
    const float* __restrict__ ex, const float* __restrict__ ey)
{
    const int bz    = blockIdx.z;
    const int b     = bz & 7;
    const int which = bz >> 3;
    const float* E = (which ? ey : ex) + (size_t)b*KDIM*VDIM;
    const float* F = (which ? fy : fx) + (size_t)b*VDIM*CDIM;
    float*       C = (which ? g_Bc : g_A) + (size_t)b*KDIM*CDIM;

    const int m0 = blockIdx.y * 64;
    const int n0 = blockIdx.x * 64;

    __shared__ float As[8][64];   // As[v][k]
    __shared__ float Bs[8][64];   // Bs[v][c]

    const int tid = threadIdx.x;
    const int tx  = tid & 15;     // n block (4 cols)
    const int ty  = tid >> 4;     // m block (4 rows)

    const bool isA = tid < 128;
    const int  t2  = tid & 127;
    const int  lrow = t2 >> 1;          // A: k row 0..63
    const int  lv4  = (t2 & 1) * 4;     // A: v offset 0/4
    const int  fvr  = t2 >> 4;          // B: v row 0..7
    const int  fc4  = (t2 & 15) * 4;    // B: c offset

    float acc[4][4];
    #pragma unroll
    for (int i = 0; i < 4; ++i)
        #pragma unroll
        for (int j = 0; j < 4; ++j) acc[i][j] = 0.f;

    // prefetch v0 = 0
    float4 pre = make_float4(0.f,0.f,0.f,0.f);
    if (isA) {
        if (m0 + lrow < KDIM)
            pre = *reinterpret_cast<const float4*>(E + (size_t)(m0 + lrow)*VDIM + lv4);
    } else {
        pre = *reinterpret_cast<const float4*>(F + (size_t)fvr*CDIM + n0 + fc4);
    }

    for (int v0 = 0; v0 < VDIM; v0 += 8) {
        __syncthreads();
        if (isA) {
            As[lv4+0][lrow] = pre.x; As[lv4+1][lrow] = pre.y;
            As[lv4+2][lrow] = pre.z; As[lv4+3][lrow] = pre.w;
        } else {
            *reinterpret_cast<float4*>(&Bs[fvr][fc4]) = pre;
        }
        __syncthreads();

        const int vn = v0 + 8;
        if (vn < VDIM) {
            if (isA) {
                pre = make_float4(0.f,0.f,0.f,0.f);
                if (m0 + lrow < KDIM)
                    pre = *reinterpret_cast<const float4*>(E + (size_t)(m0 + lrow)*VDIM + vn + lv4);
            } else {
                pre = *reinterpret_cast<const float4*>(F + (size_t)(vn + fvr)*CDIM + n0 + fc4);
            }
        }

        #pragma unroll
        for (int kk = 0; kk < 8; ++kk) {
            float4 a  = *reinterpret_cast<const float4*>(&As[kk][ty*4]);
            float4 bb = *reinterpret_cast<const float4*>(&Bs[kk][tx*4]);
            float am[4] = {a.x,a.y,a.z,a.w};
            float bn[4] = {bb.x,bb.y,bb.z,bb.w};
            #pragma unroll
            for (int i2 = 0; i2 < 4; ++i2)
                #pragma unroll
                for (int j2 = 0; j2 < 4; ++j2)
                    acc[i2][j2] = fmaf(am[i2], bn[j2], acc[i2][j2]);
        }
    }

    #pragma unroll
    for (int i2 = 0; i2 < 4; ++i2) {
        int k = m0 + ty*4 + i2;
        if (k < KDIM) {
            float4 v = make_float4(acc[i2][0], acc[i2][1], acc[i2][2], acc[i2][3]);
            *reinterpret_cast<float4*>(C + (size_t)k*CDIM + n0 + tx*4) = v;
        }
    }
}

// ---------------------------------------------------------------------------
// Kernel 2: S[b] = A A^T, R[b] = Bc A^T   (200x200x256)
// ---------------------------------------------------------------------------
__global__ __launch_bounds__(256) void k_gemm_gram()
{
    const int bz    = blockIdx.z;
    const int b     = bz & 7;
    const int which = bz >> 3;
    const float* X = (which ? g_Bc : g_A) + (size_t)b*KDIM*CDIM;
    const float* Y = g_A + (size_t)b*KDIM*CDIM;
    float*       C = (which ? g_R : g_S) + (size_t)b*KDIM*KDIM;

    const int m0 = blockIdx.y * 64;
    const int n0 = blockIdx.x * 64;

    __shared__ float As[16][64];
    __shared__ float Bs[16][64];

    const int tid = threadIdx.x;
    const int tx  = tid & 15;
    const int ty  = tid >> 4;
    const int lr  = tid >> 2;
    const int lc4 = (tid & 3) * 4;

    float acc[4][4];
    #pragma unroll
    for (int i = 0; i < 4; ++i)
        #pragma unroll
        for (int j = 0; j < 4; ++j) acc[i][j] = 0.f;

    for (int c0 = 0; c0 < CDIM; c0 += 16) {
        float4 xa = make_float4(0.f,0.f,0.f,0.f), yb = make_float4(0.f,0.f,0.f,0.f);
        if (m0 + lr < KDIM) xa = *reinterpret_cast<const float4*>(X + (size_t)(m0+lr)*CDIM + c0 + lc4);
        if (n0 + lr < KDIM) yb = *reinterpret_cast<const float4*>(Y + (size_t)(n0+lr)*CDIM + c0 + lc4);
        __syncthreads();
        As[lc4+0][lr] = xa.x; As[lc4+1][lr] = xa.y; As[lc4+2][lr] = xa.z; As[lc4+3][lr] = xa.w;
        Bs[lc4+0][lr] = yb.x; Bs[lc4+1][lr] = yb.y; Bs[lc4+2][lr] = yb.z; Bs[lc4+3][lr] = yb.w;
        __syncthreads();
        #pragma unroll
        for (int kk = 0; kk < 16; ++kk) {
            float4 a  = *reinterpret_cast<const float4*>(&As[kk][ty*4]);
            float4 bb = *reinterpret_cast<const float4*>(&Bs[kk][tx*4]);
            float am[4] = {a.x,a.y,a.z,a.w}, bn[4] = {bb.x,bb.y,bb.z,bb.w};
            #pragma unroll
            for (int i2 = 0; i2 < 4; ++i2)
                #pragma unroll
                for (int j2 = 0; j2 < 4; ++j2)
                    acc[i2][j2] = fmaf(am[i2], bn[j2], acc[i2][j2]);
        }
    }

    for (int i2 = 0; i2 < 4; ++i2) {
        int k = m0 + ty*4 + i2;
        if (k >= KDIM) continue;
        for (int j2 = 0; j2 < 4; ++j2) {
            int l = n0 + tx*4 + j2;
            if (l >= KDIM) continue;
            C[(size_t)k*KDIM + l] = acc[i2][j2];
        }
    }
}

// ---------------------------------------------------------------------------
// Kernel 3: per-(b,i) SPD solve. Blocked Cholesky on packed lower triangle.
// 256 threads, ~98.6 KB smem -> 2 CTAs/SM. grid (200, 8).
// Phases per panel: [warp0 diag-block factor] -> [parallel row TRSM] ->
//                   [balanced 4x4-tiled rank-20 trailing update]
// Solves: blocked (warp0 register diag solve + parallel rank-20 update).
// ---------------------------------------------------------------------------
#define MSH_FLOATS 20400
#define SOLVE_SMEM_FLOATS (MSH_FLOATS + NB*KDIM + KDIM + KDIM + NB + NB*NB + 32)
#define SOLVE_SMEM_BYTES  (SOLVE_SMEM_FLOATS * 4)

__global__ __launch_bounds__(256, 2) void k_solve(
    const float* __restrict__ evx_all, const float* __restrict__ evy_all,
    const float* __restrict__ p_gamma, const float* __restrict__ p_lambda,
    float* __restrict__ out)
{
    extern __shared__ float sh[];
    float* Msh  = sh;                      // packed lower triangle, 20400
    float* Psh  = Msh + MSH_FLOATS;        // [NB][KDIM] panel, transposed
    float* rhs  = Psh + NB*KDIM;           // [200]
    float* dinv = rhs + KDIM;              // [200]
    float* xblk = dinv + KDIM;             // [20]  (16B aligned: offset 24800)
    float* Dblk = xblk + NB;               // [NB][NB] compact diag block
    float* red  = Dblk + NB*NB;            // [32]

    const int irow = blockIdx.x;
    const int b    = blockIdx.y;
    const int tid  = threadIdx.x;
    const int lane = tid & 31;
    const int wid  = tid >> 5;

    const float* evx = evx_all + b*KDIM;
    const float* evy = evy_all + b*KDIM;

    const float graw  = p_gamma[0];
    const float lraw  = p_lambda[0];
    const float gamma = 1.f / (1.f + expf(-graw));
    const float sp    = fmaxf(lraw, 0.f) + log1pf(expf(-fabsf(lraw)));
    float lmbda = 10.f + sp * (1000.f - 10.f) / 1000.f;
    lmbda = fminf(fmaxf(lmbda, 10.f), 1000.f);

    // scaling = max over evals
    float mv = 0.f;
    for (int j = tid; j < KDIM; j += 256) mv = fmaxf(mv, fmaxf(evx[j], evy[j]));
    #pragma unroll
    for (int o = 16; o > 0; o >>= 1) mv = fmaxf(mv, __shfl_xor_sync(0xffffffffu, mv, o));
    if (lane == 0) red[wid] = mv;
    __syncthreads();
    if (tid == 0) {
        float m2 = red[0];
        for (int w = 1; w < 8; ++w) m2 = fmaxf(m2, red[w]);
        red[0] = m2;
    }
    __syncthreads();
    const float scaling = red[0];

    const float gx = powf(evx[irow] / scaling, gamma);
    const float dx = 1.f / (gx*gx + 1.f);

    // Load lower triangle of S (packed), row-per-warp round robin
    const float* Sb = g_S + (size_t)b*KDIM*KDIM;
    for (int r = wid; r < KDIM; r += 8) {
        const int base = offr(r);
        const float* srow = Sb + (size_t)r*KDIM;
        for (int c = lane; c <= r; c += 32) Msh[base + c] = srow[c];
    }
    if (tid < KDIM)
        rhs[tid] = g_R[(size_t)b*KDIM*KDIM + (size_t)irow*KDIM + tid];
    __syncthreads();

    // Diagonal shift
    if (tid < KDIM) {
        const int r = tid;
        float gy  = powf(evy[r] / scaling, gamma);
        float dy  = 1.f / (gy*gy + 1.f);
        float mre = gy*dy - gx*dx;
        float mim = dy - dx;
        Msh[offr(r) + r] += lmbda * (mre*mre + mim*mim);
    }
    __syncthreads();

    // ---------------- Blocked Cholesky ----------------
    for (int p = 0; p < NPAN; ++p) {
        const int k0   = p * NB;
        const int kend = k0 + NB;

        // 1) diag block factor (warp 0, register-resident, shfl)
        if (wid == 0 && lane < NB) {
            const int row = k0 + lane;
            const int rb  = offr(row);
            float a[NB];
            for (int m = 0; m <= lane; ++m) a[m] = Msh[rb + k0 + m];
            #pragma unroll
            for (int kk = 0; kk < NB; ++kk) {
                float dval = __shfl_sync(0x000FFFFFu, a[kk], kk);
                float s    = sqrtf(dval);
                float inv  = 1.f / s;
                if (lane == kk) { a[kk] = s; dinv[k0+kk] = inv; }
                if (lane > kk)  a[kk] *= inv;
                for (int m = kk + 1; m < NB; ++m) {
                    float Lmk = __shfl_sync(0x000FFFFFu, a[kk], m);
                    if (lane >= m) a[m] -= a[kk] * Lmk;
                }
            }
            for (int m = 0; m <= lane; ++m) {
                Msh[rb + k0 + m]     = a[m];
                Dblk[lane*NB + m]    = a[m];
            }
        }
        __syncthreads();

        const int t = KDIM - kend;
        if (t > 0) {
            // 2) TRSM: row i of panel solved against diag block (thread per row)
            for (int r = tid; r < t; r += 256) {
                const int i  = kend + r;
                const int ib = offr(i) + k0;
                float rowreg[NB];
                #pragma unroll
                for (int m4 = 0; m4 < NB; m4 += 4) {
                    float4 v = *reinterpret_cast<const float4*>(&Msh[ib + m4]);
                    rowreg[m4+0]=v.x; rowreg[m4+1]=v.y; rowreg[m4+2]=v.z; rowreg[m4+3]=v.w;
                }
                #pragma unroll
                for (int j = 0; j < NB; ++j) {
                    float s = rowreg[j];
                    for (int m = 0; m < j; ++m) s -= rowreg[m] * Dblk[j*NB + m];
                    rowreg[j] = s * dinv[k0 + j];
                }
                #pragma unroll
                for (int m4 = 0; m4 < NB; m4 += 4) {
                    *reinterpret_cast<float4*>(&Msh[ib + m4]) =
                        make_float4(rowreg[m4+0], rowreg[m4+1], rowreg[m4+2], rowreg[m4+3]);
                }
                #pragma unroll
                for (int j = 0; j < NB; ++j) Psh[j*KDIM + r] = rowreg[j];
            }
            __syncthreads();

            // 3) trailing update: lower triangle of t x t, balanced 4x4 tiles
            const int nbk  = t >> 2;
            const int nblk = (nbk * (nbk + 1)) >> 1;
            for (int bidx = tid; bidx < nblk; bidx += 256) {
                int ri = (int)((__fsqrt_rn(8.f * (float)bidx + 1.f) - 1.f) * 0.5f);
                while ((ri + 1) * (ri + 2) / 2 <= bidx) ++ri;
                while (ri * (ri + 1) / 2 > bidx) --ri;
                const int cj = bidx - ri * (ri + 1) / 2;

                float acc[4][4];
                #pragma unroll
                for (int i2 = 0; i2 < 4; ++i2)
                    #pragma unroll
                    for (int j2 = 0; j2 < 4; ++j2) acc[i2][j2] = 0.f;

                #pragma unroll
                for (int k = 0; k < NB; ++k) {
                    float4 av = *reinterpret_cast<const float4*>(&Psh[k*KDIM + 4*ri]);
                    float4 bv = *reinterpret_cast<const float4*>(&Psh[k*KDIM + 4*cj]);
                    float am[4] = {av.x,av.y,av.z,av.w};
                    float bn[4] = {bv.x,bv.y,bv.z,bv.w};
                    #pragma unroll
                    for (int i2 = 0; i2 < 4; ++i2)
                        #pragma unroll
                        for (int j2 = 0; j2 < 4; ++j2)
                            acc[i2][j2] = fmaf(am[i2], bn[j2], acc[i2][j2]);
                }
                #pragma unroll
                for (int i2 = 0; i2 < 4; ++i2) {
                    const int row = kend + 4*ri + i2;
                    float4* cp = reinterpret_cast<float4*>(&Msh[offr(row) + kend + 4*cj]);
                    float4 c = *cp;
                    c.x -= acc[i2][0]; c.y -= acc[i2][1];
                    c.z -= acc[i2][2]; c.w -= acc[i2][3];
                    *cp = c;
                }
            }
        }
        __syncthreads();
    }

    // ---------------- Forward solve: L y = rhs ----------------
    for (int blk = 0; blk < NPAN; ++blk) {
        const int bk0 = blk * NB;
        if (wid == 0 && lane < NB) {
            const int rb = offr(bk0 + lane);
            float a[NB];
            for (int m = 0; m <= lane; ++m) a[m] = Msh[rb + bk0 + m];
            float r = rhs[bk0 + lane];
            #pragma unroll
            for (int m = 0; m < NB; ++m) {
                float ym = __shfl_sync(0x000FFFFFu, r, m) * dinv[bk0 + m];
                if (lane == m) r = ym;
                if (lane >  m) r -= a[m] * ym;
            }
            rhs[bk0 + lane] = r;
            xblk[lane] = r;
        }
        __syncthreads();
        for (int i = bk0 + NB + tid; i < KDIM; i += 256) {
            float s = rhs[i];
            const int ib = offr(i) + bk0;
            #pragma unroll
            for (int m4 = 0; m4 < NB; m4 += 4) {
                float4 L4 = *reinterpret_cast<const float4*>(&Msh[ib + m4]);
                float4 x4 = *reinterpret_cast<const float4*>(&xblk[m4]);
                s -= L4.x*x4.x + L4.y*x4.y + L4.z*x4.z + L4.w*x4.w;
            }
            rhs[i] = s;
        }
        __syncthreads();
    }

    // ---------------- Backward solve: L^T x = y ----------------
    for (int blk = NPAN - 1; blk >= 0; --blk) {
        const int bk0 = blk * NB;
        if (wid == 0 && lane < NB) {
            float a[NB];
            for (int m = lane; m < NB; ++m) a[m] = Msh[offr(bk0 + m) + bk0 + lane];
            float r = rhs[bk0 + lane];
            #pragma unroll
            for (int m = NB - 1; m >= 0; --m) {
                float xm = __shfl_sync(0x000FFFFFu, r, m) * dinv[bk0 + m];
                if (lane == m) r = xm;
                if (lane <  m) r -= a[m] * xm;
            }
            rhs[bk0 + lane] = r;
            xblk[lane] = r;
        }
        __syncthreads();
        for (int i = tid; i < bk0; i += 256) {
            float s = rhs[i];
            #pragma unroll
            for (int m = 0; m < NB; ++m) s -= Msh[offr(bk0 + m) + i] * xblk[m];
            rhs[i] = s;
        }
        __syncthreads();
    }

    for (int j = tid; j < KDIM; j += 256)
        out[((size_t)b*KDIM + irow)*KDIM + j] = rhs[j];
}

// ---------------------------------------------------------------------------
extern "C" void kernel_launch(void* const* d_in, const int* in_sizes, int n_in,
                              void* d_out, int out_size)
{
    const float* feat_x  = (const float*)d_in[0];
    const float* feat_y  = (const float*)d_in[1];
    const float* evals_x = (const float*)d_in[2];
    const float* evals_y = (const float*)d_in[3];
    const float* evtx    = (const float*)d_in[4];
    const float* evty    = (const float*)d_in[5];
    const float* graw    = (const float*)d_in[6];
    const float* lraw    = (const float*)d_in[7];
    float* out = (float*)d_out;

    k_gemm_feat<<<dim3(4, 4, 16), 256>>>(feat_x, feat_y, evtx, evty);
    k_gemm_gram<<<dim3(4, 4, 16), 256>>>();
    cudaFuncSetAttribute(k_solve, cudaFuncAttributeMaxDynamicSharedMemorySize, SOLVE_SMEM_BYTES);
    k_solve<<<dim3(KDIM, BATCH), 256, SOLVE_SMEM_BYTES>>>(evals_x, evals_y, graw, lraw, out);
}

// round 3
// speedup vs baseline: 2.0446x; 1.1483x over previous
#include <cuda_runtime.h>
#include <math.h>

#define BATCH 8
#define VDIM 5000
#define CDIM 256
#define KDIM 200
#define NB   20
#define NBP  21          // padded Dblk stride (gcd(21,32)=1)
#define NPAN (KDIM/NB)

// Scratch (device globals: no allocation allowed)
__device__ float g_A [BATCH*KDIM*CDIM];
__device__ float g_Bc[BATCH*KDIM*CDIM];
__device__ float g_S [BATCH*KDIM*KDIM];
__device__ float g_R [BATCH*KDIM*KDIM];

// Packed lower-triangle row offset, rows padded to float4. Total = 20400 floats.
__device__ __forceinline__ int offr(int i) {
    int q = i >> 2, r = i & 3;
    return ((q + 1) * ((q << 1) + r)) << 2;
}

// ---------------------------------------------------------------------------
// Kernel 1: A[b,k,c] = sum_v E[b,k,v] * F[b,v,c]   (M=200, N=256, K=5000)
// BM=64, BN=64, BK=8, 256 threads, 4x4 register tile, double-buffered smem.
// grid (4, 4, 16) ; z = b + 8*which
// ---------------------------------------------------------------------------
__global__ __launch_bounds__(256) void k_gemm_feat(
    const float* __restrict__ fx, const float* __restrict__ fy,
    const float* __restrict__ ex, const float* __restrict__ ey)
{
    const int bz    = blockIdx.z;
    const int b     = bz & 7;
    const int which = bz >> 3;
    const float* E = (which ? ey : ex) + (size_t)b*KDIM*VDIM;
    const float* F = (which ? fy : fx) + (size_t)b*VDIM*CDIM;
    float*       C = (which ? g_Bc : g_A) + (size_t)b*KDIM*CDIM;

    const int m0 = blockIdx.y * 64;
    const int n0 = blockIdx.x * 64;

    __shared__ float As[2][8][64];   // As[buf][v][k]
    __shared__ float Bs[2][8][64];   // Bs[buf][v][c]

    const int tid = threadIdx.x;
    const int tx  = tid & 15;
    const int ty  = tid >> 4;

    const bool isA = tid < 128;
    const int  t2  = tid & 127;
    const int  lrow = t2 >> 1;
    const int  lv4  = (t2 & 1) * 4;
    const int  fvr  = t2 >> 4;
    const int  fc4  = (t2 & 15) * 4;
    const bool arow_ok = (m0 + lrow < KDIM);

    float acc[4][4];
    #pragma unroll
    for (int i = 0; i < 4; ++i)
        #pragma unroll
        for (int j = 0; j < 4; ++j) acc[i][j] = 0.f;

    // preload tile 0 into buf 0
    {
        float4 pre = make_float4(0.f,0.f,0.f,0.f);
        if (isA) {
            if (arow_ok)
                pre = *reinterpret_cast<const float4*>(E + (size_t)(m0 + lrow)*VDIM + lv4);
            As[0][lv4+0][lrow] = pre.x; As[0][lv4+1][lrow] = pre.y;
            As[0][lv4+2][lrow] = pre.z; As[0][lv4+3][lrow] = pre.w;
        } else {
            pre = *reinterpret_cast<const float4*>(F + (size_t)fvr*CDIM + n0 + fc4);
            *reinterpret_cast<float4*>(&Bs[0][fvr][fc4]) = pre;
        }
    }
    __syncthreads();

    int buf = 0;
    for (int v0 = 0; v0 < VDIM; v0 += 8) {
        const int vn = v0 + 8;
        const bool has = vn < VDIM;
        float4 nxt = make_float4(0.f,0.f,0.f,0.f);
        if (has) {
            if (isA) {
                if (arow_ok)
                    nxt = *reinterpret_cast<const float4*>(E + (size_t)(m0 + lrow)*VDIM + vn + lv4);
            } else {
                nxt = *reinterpret_cast<const float4*>(F + (size_t)(vn + fvr)*CDIM + n0 + fc4);
            }
        }

        #pragma unroll
        for (int kk = 0; kk < 8; ++kk) {
            float4 a  = *reinterpret_cast<const float4*>(&As[buf][kk][ty*4]);
            float4 bb = *reinterpret_cast<const float4*>(&Bs[buf][kk][tx*4]);
            float am[4] = {a.x,a.y,a.z,a.w};
            float bn[4] = {bb.x,bb.y,bb.z,bb.w};
            #pragma unroll
            for (int i2 = 0; i2 < 4; ++i2)
                #pragma unroll
                for (int j2 = 0; j2 < 4; ++j2)
                    acc[i2][j2] = fmaf(am[i2], bn[j2], acc[i2][j2]);
        }

        if (has) {
            const int nb = buf ^ 1;
            if (isA) {
                As[nb][lv4+0][lrow] = nxt.x; As[nb][lv4+1][lrow] = nxt.y;
                As[nb][lv4+2][lrow] = nxt.z; As[nb][lv4+3][lrow] = nxt.w;
            } else {
                *reinterpret_cast<float4*>(&Bs[nb][fvr][fc4]) = nxt;
            }
        }
        __syncthreads();
        buf ^= 1;
    }

    #pragma unroll
    for (int i2 = 0; i2 < 4; ++i2) {
        int k = m0 + ty*4 + i2;
        if (k < KDIM) {
            float4 v = make_float4(acc[i2][0], acc[i2][1], acc[i2][2], acc[i2][3]);
            *reinterpret_cast<float4*>(C + (size_t)k*CDIM + n0 + tx*4) = v;
        }
    }
}

// ---------------------------------------------------------------------------
// Kernel 2: S[b] = A A^T, R[b] = Bc A^T   (200x200x256)
// ---------------------------------------------------------------------------
__global__ __launch_bounds__(256) void k_gemm_gram()
{
    const int bz    = blockIdx.z;
    const int b     = bz & 7;
    const int which = bz >> 3;
    const float* X = (which ? g_Bc : g_A) + (size_t)b*KDIM*CDIM;
    const float* Y = g_A + (size_t)b*KDIM*CDIM;
    float*       C = (which ? g_R : g_S) + (size_t)b*KDIM*KDIM;

    const int m0 = blockIdx.y * 64;
    const int n0 = blockIdx.x * 64;

    __shared__ float As[16][64];
    __shared__ float Bs[16][64];

    const int tid = threadIdx.x;
    const int tx  = tid & 15;
    const int ty  = tid >> 4;
    const int lr  = tid >> 2;
    const int lc4 = (tid & 3) * 4;

    float acc[4][4];
    #pragma unroll
    for (int i = 0; i < 4; ++i)
        #pragma unroll
        for (int j = 0; j < 4; ++j) acc[i][j] = 0.f;

    for (int c0 = 0; c0 < CDIM; c0 += 16) {
        float4 xa = make_float4(0.f,0.f,0.f,0.f), yb = make_float4(0.f,0.f,0.f,0.f);
        if (m0 + lr < KDIM) xa = *reinterpret_cast<const float4*>(X + (size_t)(m0+lr)*CDIM + c0 + lc4);
        if (n0 + lr < KDIM) yb = *reinterpret_cast<const float4*>(Y + (size_t)(n0+lr)*CDIM + c0 + lc4);
        __syncthreads();
        As[lc4+0][lr] = xa.x; As[lc4+1][lr] = xa.y; As[lc4+2][lr] = xa.z; As[lc4+3][lr] = xa.w;
        Bs[lc4+0][lr] = yb.x; Bs[lc4+1][lr] = yb.y; Bs[lc4+2][lr] = yb.z; Bs[lc4+3][lr] = yb.w;
        __syncthreads();
        #pragma unroll
        for (int kk = 0; kk < 16; ++kk) {
            float4 a  = *reinterpret_cast<const float4*>(&As[kk][ty*4]);
            float4 bb = *reinterpret_cast<const float4*>(&Bs[kk][tx*4]);
            float am[4] = {a.x,a.y,a.z,a.w}, bn[4] = {bb.x,bb.y,bb.z,bb.w};
            #pragma unroll
            for (int i2 = 0; i2 < 4; ++i2)
                #pragma unroll
                for (int j2 = 0; j2 < 4; ++j2)
                    acc[i2][j2] = fmaf(am[i2], bn[j2], acc[i2][j2]);
        }
    }

    for (int i2 = 0; i2 < 4; ++i2) {
        int k = m0 + ty*4 + i2;
        if (k >= KDIM) continue;
        for (int j2 = 0; j2 < 4; ++j2) {
            int l = n0 + tx*4 + j2;
            if (l >= KDIM) continue;
            C[(size_t)k*KDIM + l] = acc[i2][j2];
        }
    }
}

// ---------------------------------------------------------------------------
// Kernel 3: per-(b,i) SPD solve. Blocked Cholesky on packed lower triangle.
// 256 threads, 2 CTAs/SM. All warp-serial register arrays fully unrolled
// (compile-time indices + lane predicates) so they stay in registers.
// ---------------------------------------------------------------------------
#define MSH_FLOATS 20400
#define SOLVE_SMEM_FLOATS (MSH_FLOATS + NB*KDIM + KDIM + KDIM + NB + NB*NBP + 32)
#define SOLVE_SMEM_BYTES  (SOLVE_SMEM_FLOATS * 4)

__global__ __launch_bounds__(256, 2) void k_solve(
    const float* __restrict__ evx_all, const float* __restrict__ evy_all,
    const float* __restrict__ p_gamma, const float* __restrict__ p_lambda,
    float* __restrict__ out)
{
    extern __shared__ float sh[];
    float* Msh  = sh;                      // packed lower triangle, 20400
    float* Psh  = Msh + MSH_FLOATS;        // [NB][KDIM] panel, transposed
    float* rhs  = Psh + NB*KDIM;           // [200]
    float* dinv = rhs + KDIM;              // [200]
    float* xblk = dinv + KDIM;             // [20] (16B aligned)
    float* Dblk = xblk + NB;               // [NB][NBP]
    float* red  = Dblk + NB*NBP;           // [32]

    const int irow = blockIdx.x;
    const int b    = blockIdx.y;
    const int tid  = threadIdx.x;
    const int lane = tid & 31;
    const int wid  = tid >> 5;

    const float* evx = evx_all + b*KDIM;
    const float* evy = evy_all + b*KDIM;

    const float graw  = p_gamma[0];
    const float lraw  = p_lambda[0];
    const float gamma = 1.f / (1.f + expf(-graw));
    const float sp    = fmaxf(lraw, 0.f) + log1pf(expf(-fabsf(lraw)));
    float lmbda = 10.f + sp * (1000.f - 10.f) / 1000.f;
    lmbda = fminf(fmaxf(lmbda, 10.f), 1000.f);

    // scaling = max over evals
    float mv = 0.f;
    for (int j = tid; j < KDIM; j += 256) mv = fmaxf(mv, fmaxf(evx[j], evy[j]));
    #pragma unroll
    for (int o = 16; o > 0; o >>= 1) mv = fmaxf(mv, __shfl_xor_sync(0xffffffffu, mv, o));
    if (lane == 0) red[wid] = mv;
    __syncthreads();
    if (tid == 0) {
        float m2 = red[0];
        for (int w = 1; w < 8; ++w) m2 = fmaxf(m2, red[w]);
        red[0] = m2;
    }
    __syncthreads();
    const float scaling = red[0];

    const float gx = powf(evx[irow] / scaling, gamma);
    const float dx = 1.f / (gx*gx + 1.f);

    // Load lower triangle of S (packed), row-per-warp round robin
    const float* Sb = g_S + (size_t)b*KDIM*KDIM;
    for (int r = wid; r < KDIM; r += 8) {
        const int base = offr(r);
        const float* srow = Sb + (size_t)r*KDIM;
        for (int c = lane; c <= r; c += 32) Msh[base + c] = srow[c];
    }
    if (tid < KDIM)
        rhs[tid] = g_R[(size_t)b*KDIM*KDIM + (size_t)irow*KDIM + tid];
    __syncthreads();

    // Diagonal shift
    if (tid < KDIM) {
        const int r = tid;
        float gy  = powf(evy[r] / scaling, gamma);
        float dy  = 1.f / (gy*gy + 1.f);
        float mre = gy*dy - gx*dx;
        float mim = dy - dx;
        Msh[offr(r) + r] += lmbda * (mre*mre + mim*mim);
    }
    __syncthreads();

    const unsigned FMASK = 0x000FFFFFu;

    // ---------------- Blocked Cholesky ----------------
    for (int p = 0; p < NPAN; ++p) {
        const int k0   = p * NB;
        const int kend = k0 + NB;

        // 1) diag block factor (warp 0, lanes 0..19, fully register-resident)
        if (wid == 0 && lane < NB) {
            const int rb = offr(k0 + lane);
            float a[NB];
            #pragma unroll
            for (int m = 0; m < NB; ++m)
                a[m] = (m <= lane) ? Msh[rb + k0 + m] : 0.f;
            #pragma unroll
            for (int kk = 0; kk < NB; ++kk) {
                float dval = __shfl_sync(FMASK, a[kk], kk);
                float s    = sqrtf(dval);
                float inv  = 1.f / s;
                if (lane == kk) { a[kk] = s; dinv[k0+kk] = inv; }
                if (lane >  kk) a[kk] *= inv;
                #pragma unroll
                for (int m = kk + 1; m < NB; ++m) {
                    float Lmk = __shfl_sync(FMASK, a[kk], m);
                    if (lane >= m) a[m] = fmaf(-a[kk], Lmk, a[m]);
                }
            }
            #pragma unroll
            for (int m = 0; m < NB; ++m) {
                if (m <= lane) {
                    Msh[rb + k0 + m]   = a[m];
                    Dblk[lane*NBP + m] = a[m];
                }
            }
        }
        __syncthreads();

        const int t = KDIM - kend;
        if (t > 0) {
            // 2) TRSM: panel rows vs diag block (thread per row)
            for (int r = tid; r < t; r += 256) {
                const int i  = kend + r;
                const int ib = offr(i) + k0;
                float rowreg[NB];
                #pragma unroll
                for (int m4 = 0; m4 < NB; m4 += 4) {
                    float4 v = *reinterpret_cast<const float4*>(&Msh[ib + m4]);
                    rowreg[m4+0]=v.x; rowreg[m4+1]=v.y; rowreg[m4+2]=v.z; rowreg[m4+3]=v.w;
                }
                #pragma unroll
                for (int j = 0; j < NB; ++j) {
                    float s = rowreg[j];
                    #pragma unroll
                    for (int m = 0; m < j; ++m) s = fmaf(-rowreg[m], Dblk[j*NBP + m], s);
                    rowreg[j] = s * dinv[k0 + j];
                }
                #pragma unroll
                for (int m4 = 0; m4 < NB; m4 += 4) {
                    *reinterpret_cast<float4*>(&Msh[ib + m4]) =
                        make_float4(rowreg[m4+0], rowreg[m4+1], rowreg[m4+2], rowreg[m4+3]);
                }
                #pragma unroll
                for (int j = 0; j < NB; ++j) Psh[j*KDIM + r] = rowreg[j];
            }
            __syncthreads();

            // 3) trailing update: lower triangle of t x t, balanced 4x4 tiles
            const int nbk  = t >> 2;
            const int nblk = (nbk * (nbk + 1)) >> 1;
            for (int bidx = tid; bidx < nblk; bidx += 256) {
                int ri = (int)((__fsqrt_rn(8.f * (float)bidx + 1.f) - 1.f) * 0.5f);
                while ((ri + 1) * (ri + 2) / 2 <= bidx) ++ri;
                while (ri * (ri + 1) / 2 > bidx) --ri;
                const int cj = bidx - ri * (ri + 1) / 2;

                float acc[4][4];
                #pragma unroll
                for (int i2 = 0; i2 < 4; ++i2)
                    #pragma unroll
                    for (int j2 = 0; j2 < 4; ++j2) acc[i2][j2] = 0.f;

                #pragma unroll
                for (int k = 0; k < NB; ++k) {
                    float4 av = *reinterpret_cast<const float4*>(&Psh[k*KDIM + 4*ri]);
                    float4 bv = *reinterpret_cast<const float4*>(&Psh[k*KDIM + 4*cj]);
                    float am[4] = {av.x,av.y,av.z,av.w};
                    float bn[4] = {bv.x,bv.y,bv.z,bv.w};
                    #pragma unroll
                    for (int i2 = 0; i2 < 4; ++i2)
                        #pragma unroll
                        for (int j2 = 0; j2 < 4; ++j2)
                            acc[i2][j2] = fmaf(am[i2], bn[j2], acc[i2][j2]);
                }
                #pragma unroll
                for (int i2 = 0; i2 < 4; ++i2) {
                    const int row = kend + 4*ri + i2;
                    float4* cp = reinterpret_cast<float4*>(&Msh[offr(row) + kend + 4*cj]);
                    float4 c = *cp;
                    c.x -= acc[i2][0]; c.y -= acc[i2][1];
                    c.z -= acc[i2][2]; c.w -= acc[i2][3];
                    *cp = c;
                }
            }
        }
        __syncthreads();
    }

    // ---------------- Forward solve: L y = rhs ----------------
    for (int blk = 0; blk < NPAN; ++blk) {
        const int bk0 = blk * NB;
        if (wid == 0 && lane < NB) {
            const int rb = offr(bk0 + lane);
            float a[NB];
            #pragma unroll
            for (int m = 0; m < NB; ++m)
                a[m] = (m <= lane) ? Msh[rb + bk0 + m] : 0.f;
            float r = rhs[bk0 + lane];
            #pragma unroll
            for (int m = 0; m < NB; ++m) {
                float ym = __shfl_sync(FMASK, r, m) * dinv[bk0 + m];
                if (lane == m) r = ym;
                if (lane >  m) r = fmaf(-a[m], ym, r);
            }
            rhs[bk0 + lane] = r;
            xblk[lane] = r;
        }
        __syncthreads();
        for (int i = bk0 + NB + tid; i < KDIM; i += 256) {
            float s = rhs[i];
            const int ib = offr(i) + bk0;
            #pragma unroll
            for (int m4 = 0; m4 < NB; m4 += 4) {
                float4 L4 = *reinterpret_cast<const float4*>(&Msh[ib + m4]);
                float4 x4 = *reinterpret_cast<const float4*>(&xblk[m4]);
                s -= L4.x*x4.x + L4.y*x4.y + L4.z*x4.z + L4.w*x4.w;
            }
            rhs[i] = s;
        }
        __syncthreads();
    }

    // ---------------- Backward solve: L^T x = y ----------------
    for (int blk = NPAN - 1; blk >= 0; --blk) {
        const int bk0 = blk * NB;
        if (wid == 0 && lane < NB) {
            float a[NB];
            #pragma unroll
            for (int m = 0; m < NB; ++m)
                a[m] = (m >= lane) ? Msh[offr(bk0 + m) + bk0 + lane] : 0.f;
            float r = rhs[bk0 + lane];
            #pragma unroll
            for (int m = NB - 1; m >= 0; --m) {
                float xm = __shfl_sync(FMASK, r, m) * dinv[bk0 + m];
                if (lane == m) r = xm;
                if (lane <  m) r = fmaf(-a[m], xm, r);
            }
            rhs[bk0 + lane] = r;
            xblk[lane] = r;
        }
        __syncthreads();
        for (int i = tid; i < bk0; i += 256) {
            float s = rhs[i];
            #pragma unroll
            for (int m = 0; m < NB; ++m) s = fmaf(-Msh[offr(bk0 + m) + i], xblk[m], s);
            rhs[i] = s;
        }
        __syncthreads();
    }

    for (int j = tid; j < KDIM; j += 256)
        out[((size_t)b*KDIM + irow)*KDIM + j] = rhs[j];
}

// ---------------------------------------------------------------------------
extern "C" void kernel_launch(void* const* d_in, const int* in_sizes, int n_in,
                              void* d_out, int out_size)
{
    const float* feat_x  = (const float*)d_in[0];
    const float* feat_y  = (const float*)d_in[1];
    const float* evals_x = (const float*)d_in[2];
    const float* evals_y = (const float*)d_in[3];
    const float* evtx    = (const float*)d_in[4];
    const float* evty    = (const float*)d_in[5];
    const float* graw    = (const float*)d_in[6];
    const float* lraw    = (const float*)d_in[7];
    float* out = (float*)d_out;

    k_gemm_feat<<<dim3(4, 4, 16), 256>>>(feat_x, feat_y, evtx, evty);
    k_gemm_gram<<<dim3(4, 4, 16), 256>>>();
    cudaFuncSetAttribute(k_solve, cudaFuncAttributeMaxDynamicSharedMemorySize, SOLVE_SMEM_BYTES);
    k_solve<<<dim3(KDIM, BATCH), 256, SOLVE_SMEM_BYTES>>>(evals_x, evals_y, graw, lraw, out);
}